// round 1
// baseline (speedup 1.0000x reference)
#include <cuda_runtime.h>
#include <stdint.h>

// SparseGather: out[m, i, j, c] = inputs[n_m, y0_m + i, x0_m + j, c]
// inputs: (N=4, H=512, W=512, C=64) fp32
// active_block_indices: (M=4096, 3) int32 -> (n, by, bx); y0 = by*16, x0 = bx*16
// out: (M, 16, 16, 64) fp32
//
// Geometry (in float4 units, C=64 -> 16 float4 per pixel):
//   C4   = 16
//   WC4  = 512 * 16 = 8192
//   HWC4 = 512 * 8192
// Input block row (fixed y): 16 pixels * 16 float4 = 256 float4 contiguous (4 KB).
// Output block: 16*16*16 = 4096 float4 contiguous (64 KB).

#define C4   16
#define WC4  (512 * C4)
#define HWC4 (512 * WC4)

__global__ __launch_bounds__(256) void sparse_gather_kernel(
    const float4* __restrict__ in,
    const int*    __restrict__ idx,
    float4*       __restrict__ out)
{
    const int m = blockIdx.x;
    const int t = threadIdx.x;  // 0..255

    const int n  = idx[3 * m + 0];
    const int by = idx[3 * m + 1];
    const int bx = idx[3 * m + 2];

    const float4* src = in
        + (size_t)n * HWC4
        + (size_t)(by * 16) * WC4
        + (size_t)(bx * 16) * C4;

    float4* dst = out + (size_t)m * (16 * 256);

    // 16 rows; each row = 256 contiguous float4 on both sides.
    // Fully unrolled -> 16 independent LDG.128 front-batched by ptxas (MLP ~16).
    float4 v[16];
    #pragma unroll
    for (int r = 0; r < 16; ++r) {
        v[r] = src[(size_t)r * WC4 + t];
    }
    #pragma unroll
    for (int r = 0; r < 16; ++r) {
        dst[r * 256 + t] = v[r];
    }
}

extern "C" void kernel_launch(void* const* d_in, const int* in_sizes, int n_in,
                              void* d_out, int out_size)
{
    const float4* in  = (const float4*)d_in[0];
    const int*    idx = (const int*)d_in[2];           // active_block_indices
    float4*       out = (float4*)d_out;

    const int M = in_sizes[2] / 3;                     // 4096

    sparse_gather_kernel<<<M, 256>>>(in, idx, out);
}

// round 2
// speedup vs baseline: 1.0290x; 1.0290x over previous
#include <cuda_runtime.h>
#include <stdint.h>

// SparseGather: out[m, i, j, c] = inputs[n_m, y0_m + i, x0_m + j, c]
// inputs: (N=4, H=512, W=512, C=64) fp32
// active_block_indices: (M=4096, 3) int32 -> (n, by, bx); y0 = by*16, x0 = bx*16
// out: (M, 16, 16, 64) fp32
//
// Units of float4 (C=64 -> 16 float4 per pixel):
//   C4   = 16
//   WC4  = 512 * 16 = 8192   (row stride, float4)
//   HWC4 = 512 * WC4         (image stride, float4)
// One input block row (fixed y): 256 contiguous float4 (4 KB).
// One output block: 4096 contiguous float4 (64 KB).
//
// R2 layout: 2 CTAs per block (8 rows each), 256 threads, 8 front-batched
// LDG.128 per thread (MLP_p1=8), evict-first stores (__stcs) so the 268 MB
// output stream doesn't evict reusable input lines from L2.

#define C4   16
#define WC4  (512 * C4)
#define HWC4 (512 * WC4)

__global__ __launch_bounds__(256) void sparse_gather_kernel(
    const float4* __restrict__ in,
    const int*    __restrict__ idx,
    float4*       __restrict__ out)
{
    const int b  = blockIdx.x;     // 0 .. 2*M-1
    const int m  = b >> 1;         // block index
    const int r0 = (b & 1) << 3;   // row offset: 0 or 8
    const int t  = threadIdx.x;    // 0..255

    const int n  = idx[3 * m + 0];
    const int by = idx[3 * m + 1];
    const int bx = idx[3 * m + 2];

    const float4* src = in
        + (size_t)n * HWC4
        + (size_t)(by * 16 + r0) * WC4
        + (size_t)(bx * 16) * C4;

    float4* dst = out + (size_t)m * 4096 + (size_t)r0 * 256;

    // 8 rows; each row = 256 contiguous float4 on both sides.
    float4 v[8];
    #pragma unroll
    for (int r = 0; r < 8; ++r) {
        v[r] = src[(size_t)r * WC4 + t];
    }
    #pragma unroll
    for (int r = 0; r < 8; ++r) {
        __stcs(&dst[r * 256 + t], v[r]);   // streaming store, evict-first in L2
    }
}

extern "C" void kernel_launch(void* const* d_in, const int* in_sizes, int n_in,
                              void* d_out, int out_size)
{
    const float4* in  = (const float4*)d_in[0];
    const int*    idx = (const int*)d_in[2];   // active_block_indices
    float4*       out = (float4*)d_out;

    const int M = in_sizes[2] / 3;             // 4096

    sparse_gather_kernel<<<2 * M, 256>>>(in, idx, out);
}